// round 8
// baseline (speedup 1.0000x reference)
#include <cuda_runtime.h>
#include <math.h>

#define TT 512
#define BB 32
#define VV 1296
#define LL 64
#define NROWS (TT*BB)
#define JP (TT/2)      // column pairs per batch
#define RING 8

// Scratch (no allocations allowed anywhere).
// g_pb4[b][jp][l] = {pb[2l][2jp], pb[2l+1][2jp], pb[2l][2jp+1], pb[2l+1][2jp+1]}
__device__ float4        g_pb4[(size_t)BB * JP * 32];
__device__ float4        g_stats[NROWS];      // {se, lse_p, V*lse_p - sum_q, 0}
__device__ unsigned int  g_colcnt[BB * 64];   // per-batch column counters, 256B stride
__device__ double        g_sum;               // zero-initialized; reset by winner
__device__ unsigned int  g_ticket;

// ---------------------------------------------------------------------------
// Fused 3-value block sum-reduction (256 threads). Results valid on tid 0.
// ---------------------------------------------------------------------------
__device__ __forceinline__ void blk_red3(float& a, float& b, float& c)
{
    #pragma unroll
    for (int o = 16; o; o >>= 1) {
        a += __shfl_xor_sync(0xffffffffu, a, o);
        b += __shfl_xor_sync(0xffffffffu, b, o);
        c += __shfl_xor_sync(0xffffffffu, c, o);
    }
    __shared__ float sred[24];
    const int w = threadIdx.x >> 5, l = threadIdx.x & 31;
    if (l == 0) { sred[w] = a; sred[w + 8] = b; sred[w + 16] = c; }
    __syncthreads();
    if (threadIdx.x < 8) {
        a = sred[threadIdx.x];
        b = sred[threadIdx.x + 8];
        c = sred[threadIdx.x + 16];
        #pragma unroll
        for (int o = 4; o; o >>= 1) {
            a += __shfl_xor_sync(0xffu, a, o);
            b += __shfl_xor_sync(0xffu, b, o);
            c += __shfl_xor_sync(0xffu, c, o);
        }
    }
}

// ---------------------------------------------------------------------------
// Stats path: per-row softmax stats + band gather (gather loads are L1 hits
// of the row being streamed). Publishes its column via fence + counter.
// Raw values into g_pb4: the per-column log-softmax constant shifts all
// dp[.,j] equally, so the DP's strict comparisons are unchanged.
// ---------------------------------------------------------------------------
__device__ __forceinline__ void stats_path(
    int s,                                  // batch-major stats index
    const float* __restrict__ pred,
    const float* __restrict__ seq_pred,
    const int*   __restrict__ label,
    const int*   __restrict__ x_len,
    const int*   __restrict__ label_len)
{
    const int b   = s >> 9;                 // batch-major: batch b columns first
    const int t   = s & (TT - 1);
    const int row = t * BB + b;
    const int tid = threadIdx.x;

    const int C = __ldg(&x_len[b]);
    if (t >= C) return;                     // masked row: no read, no count

    const size_t base = (size_t)row * VV;
    const float4* __restrict__ sp4 = (const float4*)(seq_pred + base);
    const float4* __restrict__ p4  = (const float4*)(pred + base);
    const bool has2 = tid < (VV / 4 - 256); // 324 float4s per row

    const float4 s0 = sp4[tid];
    const float4 q0 = p4[tid];
    float4 s1, q1;
    if (has2) { s1 = sp4[tid + 256]; q1 = p4[tid + 256]; }

    // Band gather (threads 0..63): L1-hot scalar loads from this same row.
    if (tid < LL) {
        const int i = tid;
        const int R = __ldg(&label_len[b]);
        float v = __int_as_float(0xff800000);
        if (i < R && t >= i && t <= C - R + i) {
            const int lab = __ldg(&label[b * LL + i]);
            v = __ldg(&seq_pred[base + lab]);
        }
        ((float*)g_pb4)[(((size_t)b * JP + (t >> 1)) * 32 + (i >> 1)) * 4
                        + ((t & 1) * 2 + (i & 1))] = v;
    }

    float se = __expf(s0.x) + __expf(s0.y) + __expf(s0.z) + __expf(s0.w);
    float pe = __expf(q0.x) + __expf(q0.y) + __expf(q0.z) + __expf(q0.w);
    float sl = q0.x + q0.y + q0.z + q0.w;
    if (has2) {
        se += __expf(s1.x) + __expf(s1.y) + __expf(s1.z) + __expf(s1.w);
        pe += __expf(q1.x) + __expf(q1.y) + __expf(q1.z) + __expf(q1.w);
        sl += q1.x + q1.y + q1.z + q1.w;
    }

    blk_red3(se, pe, sl);   // contains __syncthreads: all block writes hb tid0

    if (tid == 0) {
        const float lse_p = __logf(pe);
        g_stats[row] = make_float4(se, lse_p, (float)VV * lse_p - sl, 0.0f);
        __threadfence();                         // release column data
        atomicAdd(&g_colcnt[b * 64], 1u);
    }
}

// ---------------------------------------------------------------------------
// DP path (one warp per batch): wait for all C columns, run the 2-col/round
// banded DP, backtrack into smem, then compute per-row CE directly:
//   ce = smooth*D - (conf - smooth)*(p_t - lse_p),  conf = exp(sp_t)/se
// Ticket winner writes the mean and resets protocol state for next replay.
// ---------------------------------------------------------------------------
__device__ __forceinline__ void dp_path(
    int b,
    const float* __restrict__ pred,
    const float* __restrict__ seq_pred,
    const int*   __restrict__ label,
    const int*   __restrict__ x_len,
    const int*   __restrict__ label_len,
    float*       __restrict__ out)
{
    __shared__ unsigned long long ch[TT];   // per-column choice ballots
    __shared__ int  srow[TT];               // backtracked row per column
    __shared__ int  labs[LL];

    const int l = threadIdx.x;
    if (l >= 32) return;

    const int C = __ldg(&x_len[b]);
    const int R = __ldg(&label_len[b]);
    const float ninf = __int_as_float(0xff800000);

    labs[l]      = __ldg(&label[b * LL + l]);
    labs[l + 32] = __ldg(&label[b * LL + l + 32]);
    if (l == 0) ch[0] = 0ULL;

    // Wait for this batch's columns (producers fence before counting).
    if (l == 0) {
        while (atomicAdd(&g_colcnt[b * 64], 0u) < (unsigned)C)
            __nanosleep(128);
        g_colcnt[b * 64] = 0u;              // reset for next replay
        __threadfence();                    // acquire
    }
    __syncwarp();

    const float4* __restrict__ pb = g_pb4 + (size_t)b * JP * 32;
    const int jlast = C - 1;                // C >= 256 always
    const int jpmax = jlast >> 1;

    // jp = 0: column 0 init (.x), column 1 single step (.z/.w)
    const float4 f0 = pb[l];
    float dlo = (l == 0) ? f0.x : ninf;
    float dhi = ninf;
    {
        float ph = __shfl_up_sync(0xffffffffu, dhi, 1);
        if (l == 0) ph = ninf;
        const bool clo = ph > dlo, chi_ = dlo > dhi;   // strict, as reference
        const unsigned blo = __ballot_sync(0xffffffffu, clo);
        const unsigned bhi = __ballot_sync(0xffffffffu, chi_);
        const float nlo = fmaxf(ph, dlo) + f0.z;
        const float nhi = fmaxf(dlo, dhi) + f0.w;
        if (l == 0) ch[1] = (unsigned long long)blo | ((unsigned long long)bhi << 32);
        dlo = nlo; dhi = nhi;
    }

    float4 buf[RING];
    #pragma unroll
    for (int k = 0; k < RING; ++k) {
        int jp = 1 + k; if (jp > jpmax) jp = jpmax;
        buf[k] = pb[jp * 32 + l];
    }

    int jp = 1, k = 0;
    while (2 * jp + 1 <= jlast) {
        const float4 f = buf[k];
        int njp = jp + RING; if (njp > jpmax) njp = jpmax;
        buf[k] = pb[njp * 32 + l];          // prefetch (clamped dup ok)
        k = (k + 1) & (RING - 1);

        float pm1 = __shfl_up_sync(0xffffffffu, f.y, 1);
        float plo = __shfl_up_sync(0xffffffffu, dlo, 1);
        float phi = __shfl_up_sync(0xffffffffu, dhi, 1);
        if (l == 0) { pm1 = ninf; plo = ninf; phi = ninf; }

        const int j = 2 * jp;
        const float a_m1 = fmaxf(plo, phi) + pm1;   // row 2l-1 recomputed
        const bool  c0   = phi > dlo;  const float a0 = fmaxf(phi, dlo) + f.x;
        const bool  c1   = dlo > dhi;  const float a1 = fmaxf(dlo, dhi) + f.y;
        const bool  c0p  = a_m1 > a0;  const float nlo = fmaxf(a_m1, a0) + f.z;
        const bool  c1p  = a0   > a1;  const float nhi = fmaxf(a0,   a1) + f.w;

        const unsigned b0 = __ballot_sync(0xffffffffu, c0);
        const unsigned b1 = __ballot_sync(0xffffffffu, c1);
        const unsigned b2 = __ballot_sync(0xffffffffu, c0p);
        const unsigned b3 = __ballot_sync(0xffffffffu, c1p);
        if (l == 0) {
            ch[j]     = (unsigned long long)b0 | ((unsigned long long)b1 << 32);
            ch[j + 1] = (unsigned long long)b2 | ((unsigned long long)b3 << 32);
        }
        dlo = nlo; dhi = nhi;
        ++jp;
    }

    if (2 * jp == jlast) {                  // even tail column
        float ph = __shfl_up_sync(0xffffffffu, dhi, 1);
        if (l == 0) ph = ninf;
        const bool clo = ph > dlo, chi_ = dlo > dhi;
        const unsigned blo = __ballot_sync(0xffffffffu, clo);
        const unsigned bhi = __ballot_sync(0xffffffffu, chi_);
        if (l == 0) ch[jlast] = (unsigned long long)blo | ((unsigned long long)bhi << 32);
    }
    __syncwarp();

    // Serial backtrack into smem (row-independent ch loads; 3-op chain).
    if (l == 0) {
        int row = R - 1;
        #pragma unroll 4
        for (int jj = C - 1; jj >= 0; --jj) {
            srow[jj] = row;
            const unsigned long long w = ch[jj];
            const int sh = ((row & 1) << 5) | (row >> 1);
            row -= (int)((w >> sh) & 1ULL);
        }
    }
    __syncwarp();

    // Per-column CE correction (warp-parallel, 2 scattered loads/column).
    double acc = 0.0;
    for (int jj = l; jj < C; jj += 32) {
        const int row  = srow[jj];
        const int tgt  = labs[row];
        const int grow = jj * BB + b;
        const size_t base = (size_t)grow * VV;
        const float4 st  = g_stats[grow];
        const float sp_t = __ldg(&seq_pred[base + tgt]);
        const float p_t  = __ldg(&pred[base + tgt]);
        const float conf   = __expf(sp_t) / st.x;
        const float smooth = (1.0f - conf) * (1.0f / (float)(VV - 1));
        acc += (double)(smooth * st.z - (conf - smooth) * (p_t - st.y));
    }
    #pragma unroll
    for (int o = 16; o; o >>= 1)
        acc += __shfl_xor_sync(0xffffffffu, acc, o);

    if (l == 0) {
        atomicAdd(&g_sum, acc);
        __threadfence();
        const unsigned tk = atomicAdd(&g_ticket, 1u);
        if (tk == BB - 1) {                 // last DP block: emit + reset
            const double total = atomicAdd(&g_sum, 0.0);
            out[0] = (float)(total / (double)NROWS);
            g_sum = 0.0;
            g_ticket = 0u;
        }
    }
}

// ---------------------------------------------------------------------------
// Single fused kernel: bids 0..31 = DP blocks (resident early, spin on their
// batch counter), bids 32.. = stats blocks in batch-major order so early
// batches complete first and their DP overlaps remaining stats waves.
// ---------------------------------------------------------------------------
__global__ void __launch_bounds__(256) fused_kernel(
    const float* __restrict__ pred,
    const float* __restrict__ seq_pred,
    const int*   __restrict__ label,
    const int*   __restrict__ x_len,
    const int*   __restrict__ label_len,
    float*       __restrict__ out)
{
    if (blockIdx.x < BB)
        dp_path(blockIdx.x, pred, seq_pred, label, x_len, label_len, out);
    else
        stats_path(blockIdx.x - BB, pred, seq_pred, label, x_len, label_len);
}

// ---------------------------------------------------------------------------
extern "C" void kernel_launch(void* const* d_in, const int* in_sizes, int n_in,
                              void* d_out, int out_size)
{
    const float* pred      = (const float*)d_in[0];
    const float* seq_pred  = (const float*)d_in[1];
    const int*   label     = (const int*)d_in[2];
    const int*   x_len     = (const int*)d_in[3];
    const int*   label_len = (const int*)d_in[4];

    fused_kernel<<<BB + NROWS, 256>>>(pred, seq_pred, label, x_len, label_len,
                                      (float*)d_out);
}

// round 9
// speedup vs baseline: 4.1492x; 4.1492x over previous
#include <cuda_runtime.h>
#include <math.h>

#define TT 512
#define BB 32
#define VV 1296
#define LL 64
#define NROWS (TT*BB)
#define JP (TT/2)      // column pairs per batch

// Scratch (no allocations allowed anywhere).
// g_pb4[b][jp][l] = {pb[2l][2jp], pb[2l+1][2jp], pb[2l][2jp+1], pb[2l+1][2jp+1]}
__device__ float4        g_pb4[(size_t)BB * JP * 32];
__device__ float4        g_stats[NROWS];      // {se, lse_p, V*lse_p - sum_q, 0}
__device__ double        g_sum;               // zero-init; reset by ticket winner
__device__ unsigned int  g_ticket;

// ---------------------------------------------------------------------------
// Fused 3-value block sum-reduction (256 threads). Results valid on tid 0.
// ---------------------------------------------------------------------------
__device__ __forceinline__ void blk_red3(float& a, float& b, float& c)
{
    #pragma unroll
    for (int o = 16; o; o >>= 1) {
        a += __shfl_xor_sync(0xffffffffu, a, o);
        b += __shfl_xor_sync(0xffffffffu, b, o);
        c += __shfl_xor_sync(0xffffffffu, c, o);
    }
    __shared__ float sred[24];
    const int w = threadIdx.x >> 5, l = threadIdx.x & 31;
    if (l == 0) { sred[w] = a; sred[w + 8] = b; sred[w + 16] = c; }
    __syncthreads();
    if (threadIdx.x < 8) {
        a = sred[threadIdx.x];
        b = sred[threadIdx.x + 8];
        c = sred[threadIdx.x + 16];
        #pragma unroll
        for (int o = 4; o; o >>= 1) {
            a += __shfl_xor_sync(0xffu, a, o);
            b += __shfl_xor_sync(0xffu, b, o);
            c += __shfl_xor_sync(0xffu, c, o);
        }
    }
}

// ---------------------------------------------------------------------------
// K1 (measured 30 us): per-row softmax stats + band gather. One block per
// (t,b) row; the gather reads the very row being streamed (L1 hits).
// Raw values into g_pb4: the per-column log-softmax constant shifts all
// dp[.,j] equally, so the DP's strict comparisons are unchanged.
// ---------------------------------------------------------------------------
__global__ void __launch_bounds__(256) stats_gather_kernel(
    const float* __restrict__ pred,
    const float* __restrict__ seq_pred,
    const int*   __restrict__ label,
    const int*   __restrict__ x_len,
    const int*   __restrict__ label_len)
{
    const int row = blockIdx.x;              // row = t*BB + b (contiguous)
    const int b   = row & (BB - 1);
    const int t   = row >> 5;
    const int tid = threadIdx.x;

    const int C = __ldg(&x_len[b]);
    if (t >= C) return;                      // masked row: skip 10KB read

    const size_t base = (size_t)row * VV;
    const float4* __restrict__ sp4 = (const float4*)(seq_pred + base);
    const float4* __restrict__ p4  = (const float4*)(pred + base);
    const bool has2 = tid < (VV / 4 - 256);  // 324 float4s per row

    const float4 s0 = sp4[tid];
    const float4 q0 = p4[tid];
    float4 s1, q1;
    if (has2) { s1 = sp4[tid + 256]; q1 = p4[tid + 256]; }

    // Band gather (threads 0..63): L1-hot scalar loads from this same row.
    if (tid < LL) {
        const int i = tid;
        const int R = __ldg(&label_len[b]);
        float v = __int_as_float(0xff800000);
        if (i < R && t >= i && t <= C - R + i) {
            const int lab = __ldg(&label[b * LL + i]);
            v = __ldg(&seq_pred[base + lab]);
        }
        ((float*)g_pb4)[(((size_t)b * JP + (t >> 1)) * 32 + (i >> 1)) * 4
                        + ((t & 1) * 2 + (i & 1))] = v;
    }

    float se = __expf(s0.x) + __expf(s0.y) + __expf(s0.z) + __expf(s0.w);
    float pe = __expf(q0.x) + __expf(q0.y) + __expf(q0.z) + __expf(q0.w);
    float sl = q0.x + q0.y + q0.z + q0.w;
    if (has2) {
        se += __expf(s1.x) + __expf(s1.y) + __expf(s1.z) + __expf(s1.w);
        pe += __expf(q1.x) + __expf(q1.y) + __expf(q1.z) + __expf(q1.w);
        sl += q1.x + q1.y + q1.z + q1.w;
    }

    blk_red3(se, pe, sl);

    if (tid == 0) {
        const float lse_p = __logf(pe);
        g_stats[row] = make_float4(se, lse_p, (float)VV * lse_p - sl, 0.0f);
    }
}

// ---------------------------------------------------------------------------
// K2: one block per batch, 256 threads.
//  - warps 1..7: double-buffer the batch's band into smem (16KB chunks,
//    latency hidden by 224-thread MLP)
//  - warp 0: 2-col/round banded DP from smem; ballots -> ch[]
//  - lane 0: backtrack -> srow[]
//  - all 256 threads: per-column CE correction
//      ce = smooth*D - (conf - smooth)*(p_t - lse_p), conf = exp(sp_t)/se
//  - ticket winner writes the mean and resets protocol state.
// ---------------------------------------------------------------------------
__global__ void __launch_bounds__(256) dp_ce_kernel(
    const float* __restrict__ pred,
    const float* __restrict__ seq_pred,
    const int*   __restrict__ label,
    const int*   __restrict__ x_len,
    const int*   __restrict__ label_len,
    float*       __restrict__ out)
{
    __shared__ float4 sb[2][32 * 32];        // 2 x 16KB band chunks (32 jp each)
    __shared__ unsigned long long ch[TT];    // per-column choice ballots
    __shared__ int    srow[TT];              // backtracked row per column
    __shared__ int    labs[LL];
    __shared__ double sredd[8];

    const int b   = blockIdx.x;
    const int tid = threadIdx.x;
    const int wid = tid >> 5;
    const int l   = tid & 31;
    const int C   = __ldg(&x_len[b]);
    const int R   = __ldg(&label_len[b]);
    const float ninf = __int_as_float(0xff800000);

    if (tid < LL) labs[tid] = __ldg(&label[b * LL + tid]);

    const float4* __restrict__ pb = g_pb4 + (size_t)b * JP * 32;
    const int jlast   = C - 1;               // C >= 256 always
    const int jpmax   = jlast >> 1;
    const int nchunks = (jpmax >> 5) + 1;    // <= 8

    // Preload chunk 0 (all threads)
    for (int i = tid; i < 1024; i += 256) sb[0][i] = pb[i];
    __syncthreads();

    float dlo = ninf, dhi = ninf;

    for (int c = 0; c < nchunks; ++c) {
        if (wid > 0) {
            if (c + 1 < nchunks) {           // stage next chunk
                const float4* __restrict__ src = pb + (c + 1) * 1024;
                float4* dst = sb[(c + 1) & 1];
                for (int i = tid - 32; i < 1024; i += 224) dst[i] = src[i];
            }
        } else {
            const float4* sbc = sb[c & 1];
            for (int s = 0; s < 32; ++s) {
                const int jp = (c << 5) + s;
                if (jp > jpmax) break;
                const float4 f = sbc[(s << 5) + l];

                if (jp == 0) {
                    // col 0 init (.x), col 1 single step (.z/.w)
                    dlo = (l == 0) ? f.x : ninf; dhi = ninf;
                    if (l == 0) ch[0] = 0ULL;
                    float ph = __shfl_up_sync(0xffffffffu, dhi, 1);
                    if (l == 0) ph = ninf;
                    const bool clo = ph > dlo, chi_ = dlo > dhi;  // strict
                    const unsigned blo = __ballot_sync(0xffffffffu, clo);
                    const unsigned bhi = __ballot_sync(0xffffffffu, chi_);
                    const float nlo = fmaxf(ph, dlo) + f.z;
                    const float nhi = fmaxf(dlo, dhi) + f.w;
                    if (l == 0)
                        ch[1] = (unsigned long long)blo |
                                ((unsigned long long)bhi << 32);
                    dlo = nlo; dhi = nhi;
                } else if (2 * jp + 1 <= jlast) {
                    // full 2-column round
                    float pm1 = __shfl_up_sync(0xffffffffu, f.y, 1);
                    float plo = __shfl_up_sync(0xffffffffu, dlo, 1);
                    float phi = __shfl_up_sync(0xffffffffu, dhi, 1);
                    if (l == 0) { pm1 = ninf; plo = ninf; phi = ninf; }

                    const int j = 2 * jp;
                    const float a_m1 = fmaxf(plo, phi) + pm1;  // row 2l-1 redo
                    const bool  c0   = phi > dlo;  const float a0 = fmaxf(phi, dlo) + f.x;
                    const bool  c1   = dlo > dhi;  const float a1 = fmaxf(dlo, dhi) + f.y;
                    const bool  c0p  = a_m1 > a0;  const float nlo = fmaxf(a_m1, a0) + f.z;
                    const bool  c1p  = a0   > a1;  const float nhi = fmaxf(a0,   a1) + f.w;

                    const unsigned b0 = __ballot_sync(0xffffffffu, c0);
                    const unsigned b1 = __ballot_sync(0xffffffffu, c1);
                    const unsigned b2 = __ballot_sync(0xffffffffu, c0p);
                    const unsigned b3 = __ballot_sync(0xffffffffu, c1p);
                    if (l == 0) {
                        ch[j]     = (unsigned long long)b0 | ((unsigned long long)b1 << 32);
                        ch[j + 1] = (unsigned long long)b2 | ((unsigned long long)b3 << 32);
                    }
                    dlo = nlo; dhi = nhi;
                } else {
                    // even tail column (2*jp == jlast)
                    float ph = __shfl_up_sync(0xffffffffu, dhi, 1);
                    if (l == 0) ph = ninf;
                    const bool clo = ph > dlo, chi_ = dlo > dhi;
                    const unsigned blo = __ballot_sync(0xffffffffu, clo);
                    const unsigned bhi = __ballot_sync(0xffffffffu, chi_);
                    if (l == 0)
                        ch[jlast] = (unsigned long long)blo |
                                    ((unsigned long long)bhi << 32);
                }
            }
        }
        __syncthreads();
    }

    // Serial backtrack (row-independent ch loads; 3-op dependent chain).
    if (tid == 0) {
        int row = R - 1;
        #pragma unroll 4
        for (int jj = jlast; jj >= 0; --jj) {
            srow[jj] = row;
            const unsigned long long w = ch[jj];
            const int sh = ((row & 1) << 5) | (row >> 1);
            row -= (int)((w >> sh) & 1ULL);
        }
    }
    __syncthreads();

    // Per-column CE correction, all 256 threads (2 scattered loads/column).
    double acc = 0.0;
    for (int jj = tid; jj < C; jj += 256) {
        const int rw   = srow[jj];
        const int tgt  = labs[rw];
        const int grow = jj * BB + b;
        const size_t base = (size_t)grow * VV;
        const float4 st  = g_stats[grow];
        const float sp_t = __ldg(&seq_pred[base + tgt]);
        const float p_t  = __ldg(&pred[base + tgt]);
        const float conf   = __expf(sp_t) / st.x;
        const float smooth = (1.0f - conf) * (1.0f / (float)(VV - 1));
        acc += (double)(smooth * st.z - (conf - smooth) * (p_t - st.y));
    }
    #pragma unroll
    for (int o = 16; o; o >>= 1)
        acc += __shfl_xor_sync(0xffffffffu, acc, o);
    if (l == 0) sredd[wid] = acc;
    __syncthreads();

    if (tid == 0) {
        const double x = sredd[0] + sredd[1] + sredd[2] + sredd[3]
                       + sredd[4] + sredd[5] + sredd[6] + sredd[7];
        atomicAdd(&g_sum, x);
        __threadfence();
        const unsigned tk = atomicAdd(&g_ticket, 1u);
        if (tk == BB - 1) {                  // last block: emit + reset
            const double total = atomicAdd(&g_sum, 0.0);
            out[0] = (float)(total / (double)NROWS);
            g_sum = 0.0;
            g_ticket = 0u;
        }
    }
}

// ---------------------------------------------------------------------------
extern "C" void kernel_launch(void* const* d_in, const int* in_sizes, int n_in,
                              void* d_out, int out_size)
{
    const float* pred      = (const float*)d_in[0];
    const float* seq_pred  = (const float*)d_in[1];
    const int*   label     = (const int*)d_in[2];
    const int*   x_len     = (const int*)d_in[3];
    const int*   label_len = (const int*)d_in[4];

    stats_gather_kernel<<<NROWS, 256>>>(pred, seq_pred, label, x_len, label_len);
    dp_ce_kernel<<<BB, 256>>>(pred, seq_pred, label, x_len, label_len,
                              (float*)d_out);
}

// round 12
// speedup vs baseline: 5.6610x; 1.3643x over previous
#include <cuda_runtime.h>
#include <math.h>

#define TT 512
#define BB 32
#define VV 1296
#define LL 64
#define NROWS (TT*BB)
#define JP (TT/2)      // column pairs per batch

// Scratch (no allocations allowed anywhere).
// g_pb4[b][jp][l] = {pb[2l][2jp], pb[2l+1][2jp], pb[2l][2jp+1], pb[2l+1][2jp+1]}
__device__ float4        g_pb4[(size_t)BB * JP * 32];
__device__ float4        g_stats[NROWS];      // {se, lse_p, V*lse_p - sum_q, 0}
__device__ double        g_sum;               // zero-init; reset by ticket winner
__device__ unsigned int  g_ticket;

// ---------------------------------------------------------------------------
// Fused 3-value block sum-reduction (256 threads). Results valid on tid 0.
// ---------------------------------------------------------------------------
__device__ __forceinline__ void blk_red3(float& a, float& b, float& c)
{
    #pragma unroll
    for (int o = 16; o; o >>= 1) {
        a += __shfl_xor_sync(0xffffffffu, a, o);
        b += __shfl_xor_sync(0xffffffffu, b, o);
        c += __shfl_xor_sync(0xffffffffu, c, o);
    }
    __shared__ float sred[24];
    const int w = threadIdx.x >> 5, l = threadIdx.x & 31;
    if (l == 0) { sred[w] = a; sred[w + 8] = b; sred[w + 16] = c; }
    __syncthreads();
    if (threadIdx.x < 8) {
        a = sred[threadIdx.x];
        b = sred[threadIdx.x + 8];
        c = sred[threadIdx.x + 16];
        #pragma unroll
        for (int o = 4; o; o >>= 1) {
            a += __shfl_xor_sync(0xffu, a, o);
            b += __shfl_xor_sync(0xffu, b, o);
            c += __shfl_xor_sync(0xffu, c, o);
        }
    }
}

// ---------------------------------------------------------------------------
// K1 (measured ~30 us): per-row softmax stats + band gather. One block per
// (t,b) row; the gather reads the very row being streamed (L1 hits).
// Raw values into g_pb4: the per-column log-softmax constant shifts all
// dp[.,j] equally, so the DP's strict comparisons are unchanged.
// ---------------------------------------------------------------------------
__global__ void __launch_bounds__(256) stats_gather_kernel(
    const float* __restrict__ pred,
    const float* __restrict__ seq_pred,
    const int*   __restrict__ label,
    const int*   __restrict__ x_len,
    const int*   __restrict__ label_len)
{
    const int row = blockIdx.x;              // row = t*BB + b (contiguous)
    const int b   = row & (BB - 1);
    const int t   = row >> 5;
    const int tid = threadIdx.x;

    const int C = __ldg(&x_len[b]);
    if (t >= C) return;                      // masked row: skip 10KB read

    const size_t base = (size_t)row * VV;
    const float4* __restrict__ sp4 = (const float4*)(seq_pred + base);
    const float4* __restrict__ p4  = (const float4*)(pred + base);
    const bool has2 = tid < (VV / 4 - 256);  // 324 float4s per row

    const float4 s0 = sp4[tid];
    const float4 q0 = p4[tid];
    float4 s1, q1;
    if (has2) { s1 = sp4[tid + 256]; q1 = p4[tid + 256]; }

    // Band gather (threads 0..63): L1-hot scalar loads from this same row.
    if (tid < LL) {
        const int i = tid;
        const int R = __ldg(&label_len[b]);
        float v = __int_as_float(0xff800000);
        if (i < R && t >= i && t <= C - R + i) {
            const int lab = __ldg(&label[b * LL + i]);
            v = __ldg(&seq_pred[base + lab]);
        }
        ((float*)g_pb4)[(((size_t)b * JP + (t >> 1)) * 32 + (i >> 1)) * 4
                        + ((t & 1) * 2 + (i & 1))] = v;
    }

    float se = __expf(s0.x) + __expf(s0.y) + __expf(s0.z) + __expf(s0.w);
    float pe = __expf(q0.x) + __expf(q0.y) + __expf(q0.z) + __expf(q0.w);
    float sl = q0.x + q0.y + q0.z + q0.w;
    if (has2) {
        se += __expf(s1.x) + __expf(s1.y) + __expf(s1.z) + __expf(s1.w);
        pe += __expf(q1.x) + __expf(q1.y) + __expf(q1.z) + __expf(q1.w);
        sl += q1.x + q1.y + q1.z + q1.w;
    }

    blk_red3(se, pe, sl);

    if (tid == 0) {
        const float lse_p = __logf(pe);
        g_stats[row] = make_float4(se, lse_p, (float)VV * lse_p - sl, 0.0f);
    }
}

// ---------------------------------------------------------------------------
// K2: one block per batch, 256 threads.
//  - warps 1..7: double-buffer the band into smem (16KB chunks)
//  - warp 0: BRANCH-FREE 2-col/round DP from smem; choices -> per-lane nibble
//    byte stores (no ballots, no lane-0 branches in the hot loop)
//  - bulk nibble->ballot-word conversion by all 8 warps
//  - lane 0: row-independent backtrack -> srow[]
//  - all 256 threads: per-column CE correction
//      ce = smooth*D - (conf - smooth)*(p_t - lse_p), conf = exp(sp_t)/se
//  - ticket winner writes the mean and resets protocol state.
// ---------------------------------------------------------------------------
__global__ void __launch_bounds__(256) dp_ce_kernel(
    const float* __restrict__ pred,
    const float* __restrict__ seq_pred,
    const int*   __restrict__ label,
    const int*   __restrict__ x_len,
    const int*   __restrict__ label_len,
    float*       __restrict__ out)
{
    __shared__ float4 sb[2][1024];           // 2 x 16KB band chunks (32 jp each)
    __shared__ unsigned long long ch[TT];    // per-column choice ballots
    __shared__ unsigned char nib[JP * 32];   // per-(pair,lane) choice nibbles
    __shared__ int    srow[TT];              // backtracked row per column
    __shared__ int    labs[LL];
    __shared__ double sredd[8];

    const int b   = blockIdx.x;
    const int tid = threadIdx.x;
    const int wid = tid >> 5;
    const int l   = tid & 31;
    const int C   = __ldg(&x_len[b]);
    const int R   = __ldg(&label_len[b]);
    const float ninf = __int_as_float(0xff800000);

    if (tid < LL) labs[tid] = __ldg(&label[b * LL + tid]);

    const float4* __restrict__ pb = g_pb4 + (size_t)b * JP * 32;
    const int jlast   = C - 1;               // C >= 256 always
    const int jpmax   = jlast >> 1;          // last pair touched
    const int jpfull  = (jlast - 1) >> 1;    // last FULL pair (2jp+1 <= jlast)
    const int nchunks = (jpmax >> 5) + 1;    // <= 8

    // Preload chunk 0 (all threads). jpmax >= 127 so chunk 0 is always full.
    for (int i = tid; i < 1024; i += 256) sb[0][i] = pb[i];
    __syncthreads();

    float dlo = ninf, dhi = ninf;

    for (int c = 0; c < nchunks; ++c) {
        if (wid > 0) {
            if (c + 1 < nchunks) {           // stage next chunk
                const float4* __restrict__ src = pb + (c + 1) * 1024;
                float4* dst = sb[(c + 1) & 1];
                int n = (jpmax + 1 - (c + 1) * 32) * 32; if (n > 1024) n = 1024;
                for (int i = tid - 32; i < n; i += 224) dst[i] = src[i];
            }
        } else {
            const float4* sbc = sb[c & 1];
            int s = 0;
            if (c == 0) {                    // prologue: col 0 init + col 1 step
                const float4 f = sbc[l];
                dlo = (l == 0) ? f.x : ninf;
                float ph = __shfl_up_sync(0xffffffffu, dhi, 1);
                if (l == 0) ph = ninf;
                const bool clo = ph > dlo, chi_ = dlo > dhi;   // strict
                const float nlo = fmaxf(ph, dlo) + f.z;
                const float nhi = fmaxf(dlo, dhi) + f.w;
                nib[l] = (unsigned char)(((int)clo << 2) | ((int)chi_ << 3));
                dlo = nlo; dhi = nhi;
                s = 1;
            }
            int send = jpfull - (c << 5) + 1; if (send > 32) send = 32;
            const int lm1 = (l > 0) ? (l - 1) : 0;       // in-bounds smem idx
            for (; s < send; ++s) {                      // branch-free hot body
                const int jp = (c << 5) + s;
                const float4 f = sbc[(s << 5) + l];
                float pm1 = sbc[(s << 5) + lm1].y;       // row 2l-1, col 2jp
                float plo = __shfl_up_sync(0xffffffffu, dlo, 1);
                float phi = __shfl_up_sync(0xffffffffu, dhi, 1);
                if (l == 0) { pm1 = ninf; plo = ninf; phi = ninf; }

                const float a_m1 = fmaxf(plo, phi) + pm1;        // row 2l-1 redo
                const bool  c0   = phi > dlo;  const float a0 = fmaxf(phi, dlo) + f.x;
                const bool  c1   = dlo > dhi;  const float a1 = fmaxf(dlo, dhi) + f.y;
                const bool  c0p  = a_m1 > a0;  const float nlo = fmaxf(a_m1, a0) + f.z;
                const bool  c1p  = a0   > a1;  const float nhi = fmaxf(a0,   a1) + f.w;

                nib[(jp << 5) + l] = (unsigned char)((int)c0 | ((int)c1 << 1)
                                   | ((int)c0p << 2) | ((int)c1p << 3));
                dlo = nlo; dhi = nhi;
            }
        }
        __syncthreads();
    }

    // Even tail column (jlast even): choices depend only on dp at col jlast-1.
    if (wid == 0 && (jlast & 1) == 0) {
        float ph = __shfl_up_sync(0xffffffffu, dhi, 1);
        if (l == 0) ph = ninf;
        const bool clo = ph > dlo, chi_ = dlo > dhi;
        nib[(jpmax << 5) + l] = (unsigned char)((int)clo | ((int)chi_ << 1));
    }
    __syncthreads();

    // Bulk nibble -> ballot-word conversion (8 warps, off the critical chain).
    for (int p = wid; p <= jpmax; p += 8) {
        const unsigned n = nib[(p << 5) + l];
        const unsigned b0 = __ballot_sync(0xffffffffu, n & 1u);
        const unsigned b1 = __ballot_sync(0xffffffffu, n & 2u);
        const unsigned b2 = __ballot_sync(0xffffffffu, n & 4u);
        const unsigned b3 = __ballot_sync(0xffffffffu, n & 8u);
        if (l == 0) {
            ch[2 * p]     = (unsigned long long)b0 | ((unsigned long long)b1 << 32);
            ch[2 * p + 1] = (unsigned long long)b2 | ((unsigned long long)b3 << 32);
        }
    }
    __syncthreads();

    // Serial backtrack (row-independent ch loads; 3-op dependent chain).
    if (tid == 0) {
        int row = R - 1;
        #pragma unroll 4
        for (int jj = jlast; jj >= 0; --jj) {
            srow[jj] = row;
            const unsigned long long w = ch[jj];
            const int sh = ((row & 1) << 5) | (row >> 1);
            row -= (int)((w >> sh) & 1ULL);
        }
    }
    __syncthreads();

    // Per-column CE correction, all 256 threads (2 scattered loads/column).
    double acc = 0.0;
    for (int jj = tid; jj < C; jj += 256) {
        const int rw   = srow[jj];
        const int tgt  = labs[rw];
        const int grow = jj * BB + b;
        const size_t base = (size_t)grow * VV;
        const float4 st  = g_stats[grow];
        const float sp_t = __ldg(&seq_pred[base + tgt]);
        const float p_t  = __ldg(&pred[base + tgt]);
        const float conf   = __expf(sp_t) / st.x;
        const float smooth = (1.0f - conf) * (1.0f / (float)(VV - 1));
        acc += (double)(smooth * st.z - (conf - smooth) * (p_t - st.y));
    }
    #pragma unroll
    for (int o = 16; o; o >>= 1)
        acc += __shfl_xor_sync(0xffffffffu, acc, o);
    if (l == 0) sredd[wid] = acc;
    __syncthreads();

    if (tid == 0) {
        const double x = sredd[0] + sredd[1] + sredd[2] + sredd[3]
                       + sredd[4] + sredd[5] + sredd[6] + sredd[7];
        atomicAdd(&g_sum, x);
        __threadfence();
        const unsigned tk = atomicAdd(&g_ticket, 1u);
        if (tk == BB - 1) {                  // last block: emit + reset
            const double total = atomicAdd(&g_sum, 0.0);
            out[0] = (float)(total / (double)NROWS);
            g_sum = 0.0;
            g_ticket = 0u;
        }
    }
}

// ---------------------------------------------------------------------------
extern "C" void kernel_launch(void* const* d_in, const int* in_sizes, int n_in,
                              void* d_out, int out_size)
{
    const float* pred      = (const float*)d_in[0];
    const float* seq_pred  = (const float*)d_in[1];
    const int*   label     = (const int*)d_in[2];
    const int*   x_len     = (const int*)d_in[3];
    const int*   label_len = (const int*)d_in[4];

    stats_gather_kernel<<<NROWS, 256>>>(pred, seq_pred, label, x_len, label_len);
    dp_ce_kernel<<<BB, 256>>>(pred, seq_pred, label, x_len, label_len,
                              (float*)d_out);
}